// round 1
// baseline (speedup 1.0000x reference)
#include <cuda_runtime.h>
#include <float.h>
#include <math.h>

// Problem constants
#define BB   64
#define NT   197
#define CT   768
#define HT   12
#define DT   64
#define LEFT 137          // int(0.7 * 196)
#define MROWS (BB*NT)     // 12608

// Scratch (device globals: allocation-free rule)
__device__ float g_q[BB*HT*NT*DT];
__device__ float g_k[BB*HT*NT*DT];
__device__ float g_v[BB*HT*NT*DT];
__device__ float g_ao[BB*NT*CT];
__device__ float g_clsh[BB*HT*(NT-1)];

// ---------------------------------------------------------------------------
// Tiled NT GEMM: C[m,n] = sum_k A[m,k]*B[n,k] + bias[n]
// BM=64, BN=128, BK=16, 256 threads, 4x8 microtile.
// mode 0: scatter into g_q/g_k/g_v per qkv reshape. mode 1: write Cout[m*N+n].
// ---------------------------------------------------------------------------
__global__ __launch_bounds__(256) void gemm_nt(
    const float* __restrict__ A, const float* __restrict__ Bw,
    const float* __restrict__ bias, int M, int N, int K, int mode,
    float* __restrict__ Cout)
{
    __shared__ float As[16][64 + 4];
    __shared__ float Bs[16][128 + 4];
    const int bm = blockIdx.y * 64;
    const int bn = blockIdx.x * 128;
    const int tid = threadIdx.x;
    const int ty = tid >> 4;     // 0..15 -> m-group of 4
    const int tx = tid & 15;     // 0..15 -> n-group of 8

    float acc[4][8];
#pragma unroll
    for (int i = 0; i < 4; i++)
#pragma unroll
        for (int j = 0; j < 8; j++) acc[i][j] = 0.f;

    const int ar = tid >> 2;            // 0..63
    const int ak = (tid & 3) * 4;       // 0,4,8,12

    for (int k0 = 0; k0 < K; k0 += 16) {
        float4 av = *(const float4*)(A + (size_t)(bm + ar) * K + k0 + ak);
        As[ak + 0][ar] = av.x; As[ak + 1][ar] = av.y;
        As[ak + 2][ar] = av.z; As[ak + 3][ar] = av.w;
#pragma unroll
        for (int rr = 0; rr < 2; rr++) {
            int f = tid + rr * 256;
            int br = f >> 2;            // 0..127
            int bk = (f & 3) * 4;
            float4 bv = *(const float4*)(Bw + (size_t)(bn + br) * K + k0 + bk);
            Bs[bk + 0][br] = bv.x; Bs[bk + 1][br] = bv.y;
            Bs[bk + 2][br] = bv.z; Bs[bk + 3][br] = bv.w;
        }
        __syncthreads();
#pragma unroll
        for (int kk = 0; kk < 16; kk++) {
            float4 a  = *(const float4*)&As[kk][ty * 4];
            float4 b0 = *(const float4*)&Bs[kk][tx * 8];
            float4 b1 = *(const float4*)&Bs[kk][tx * 8 + 4];
            float ax[4] = {a.x, a.y, a.z, a.w};
            float bx[8] = {b0.x, b0.y, b0.z, b0.w, b1.x, b1.y, b1.z, b1.w};
#pragma unroll
            for (int i = 0; i < 4; i++)
#pragma unroll
                for (int j = 0; j < 8; j++) acc[i][j] += ax[i] * bx[j];
        }
        __syncthreads();
    }

    const int n0 = bn + tx * 8;
    if (mode == 0) {
        // qkv linear column n -> (which, h, d): n = which*768 + h*64 + d
        const int which = n0 / CT;
        const int h = (n0 % CT) / DT;
        const int d0 = n0 % DT;        // 8 consecutive d's, stays within one head
        float* dst = (which == 0) ? g_q : (which == 1) ? g_k : g_v;
#pragma unroll
        for (int i = 0; i < 4; i++) {
            int m = bm + ty * 4 + i;
            int b = m / NT, tok = m % NT;
            float* row = dst + (((size_t)(b * HT + h)) * NT + tok) * DT + d0;
#pragma unroll
            for (int j = 0; j < 8; j++) row[j] = acc[i][j] + bias[n0 + j];
        }
    } else {
#pragma unroll
        for (int i = 0; i < 4; i++) {
            int m = bm + ty * 4 + i;
            float* row = Cout + (size_t)m * N + n0;
#pragma unroll
            for (int j = 0; j < 8; j++) row[j] = acc[i][j] + bias[n0 + j];
        }
    }
}

// ---------------------------------------------------------------------------
// Attention: one block per (b,h). K,V staged in SMEM (68-float padded rows).
// Each warp processes q rows strided by 8. Softmax + PV per row.
// Row 0's probabilities (keys 1..196) go to g_clsh for the EViT cls score.
// ---------------------------------------------------------------------------
#define KPAD 68
__global__ __launch_bounds__(256) void attn_kernel()
{
    extern __shared__ float sm[];
    float* Ks = sm;                       // 197*68
    float* Vs = Ks + NT * KPAD;           // 197*68
    float* qs = Vs + NT * KPAD;           // 8*64
    float* ps = qs + 8 * 64;              // 8*197

    const int bh = blockIdx.x;            // b*12 + h
    const float* Qg = g_q + (size_t)bh * NT * DT;
    const float* Kg = g_k + (size_t)bh * NT * DT;
    const float* Vg = g_v + (size_t)bh * NT * DT;

    const int tid = threadIdx.x, lane = tid & 31, w = tid >> 5;

    // stage K and V (float4, 16 float4 per row)
    for (int i = tid; i < NT * 16; i += 256) {
        int r = i >> 4, c4 = (i & 15) * 4;
        *(float4*)(Ks + r * KPAD + c4) = *(const float4*)(Kg + r * DT + c4);
        *(float4*)(Vs + r * KPAD + c4) = *(const float4*)(Vg + r * DT + c4);
    }
    __syncthreads();

    const float scale = 0.125f;           // 64^-0.5
    const int b = bh / HT, h = bh % HT;

    for (int qr = w; qr < NT; qr += 8) {
        // load q row into per-warp smem
        qs[w * 64 + lane]      = Qg[qr * DT + lane];
        qs[w * 64 + lane + 32] = Qg[qr * DT + lane + 32];
        __syncwarp();

        float sarr[7];
        float mx = -FLT_MAX;
#pragma unroll
        for (int t = 0; t < 7; t++) {
            int j = lane + t * 32;
            float acc = -FLT_MAX;
            if (j < NT) {
                float a = 0.f;
                const float* kr = Ks + j * KPAD;
                const float* qr2 = qs + w * 64;
#pragma unroll
                for (int d4 = 0; d4 < 16; d4++) {
                    float4 qv = *(const float4*)(qr2 + d4 * 4);
                    float4 kv = *(const float4*)(kr + d4 * 4);
                    a += qv.x * kv.x + qv.y * kv.y + qv.z * kv.z + qv.w * kv.w;
                }
                acc = a * scale;
            }
            sarr[t] = acc;
            mx = fmaxf(mx, acc);
        }
#pragma unroll
        for (int o = 16; o; o >>= 1) mx = fmaxf(mx, __shfl_xor_sync(~0u, mx, o));

        float sum = 0.f;
#pragma unroll
        for (int t = 0; t < 7; t++) {
            int j = lane + t * 32;
            float e = (j < NT) ? __expf(sarr[t] - mx) : 0.f;
            sarr[t] = e;
            sum += e;
        }
#pragma unroll
        for (int o = 16; o; o >>= 1) sum += __shfl_xor_sync(~0u, sum, o);
        float inv = 1.f / sum;

#pragma unroll
        for (int t = 0; t < 7; t++) {
            int j = lane + t * 32;
            if (j < NT) {
                float p = sarr[t] * inv;
                ps[w * NT + j] = p;
                if (qr == 0 && j >= 1)
                    g_clsh[(size_t)bh * (NT - 1) + (j - 1)] = p;
            }
        }
        __syncwarp();

        // PV: out[d] = sum_j p_j * V[j][d], d = lane, lane+32
        float o0 = 0.f, o1 = 0.f;
        const float* pr = ps + w * NT;
        for (int j = 0; j < NT; j++) {
            float p = pr[j];
            o0 += p * Vs[j * KPAD + lane];
            o1 += p * Vs[j * KPAD + lane + 32];
        }
        float* orow = g_ao + ((size_t)(b * NT + qr)) * CT + h * DT;
        orow[lane]      = o0;
        orow[lane + 32] = o1;
        __syncwarp();
    }
}

// ---------------------------------------------------------------------------
// Deterministic head-mean of cls attention -> out_cls [B, 196]
// ---------------------------------------------------------------------------
__global__ void cls_reduce(float* __restrict__ out_cls)
{
    int bb = blockIdx.x;
    int j = threadIdx.x;
    if (j < NT - 1) {
        float s = 0.f;
#pragma unroll
        for (int hh = 0; hh < HT; hh++)
            s += g_clsh[((size_t)(bb * HT + hh)) * (NT - 1) + j];
        out_cls[bb * (NT - 1) + j] = s * (1.f / 12.f);
    }
}

// ---------------------------------------------------------------------------
// Top-k per batch: bitonic sort 256 (padded) by (val desc, idx asc),
// then write idx (as float) and broadcast index [137,768].
// ---------------------------------------------------------------------------
__global__ __launch_bounds__(256) void topk_kernel(
    const float* __restrict__ cls, float* __restrict__ out_idx,
    float* __restrict__ out_index)
{
    __shared__ float v[256];
    __shared__ int   id[256];
    const int bb = blockIdx.x;
    const int t = threadIdx.x;

    v[t]  = (t < NT - 1) ? cls[bb * (NT - 1) + t] : -FLT_MAX;
    id[t] = t;
    __syncthreads();

    for (int ksz = 2; ksz <= 256; ksz <<= 1) {
        for (int j = ksz >> 1; j > 0; j >>= 1) {
            int ixj = t ^ j;
            if (ixj > t) {
                float v1 = v[t], v2 = v[ixj];
                int i1 = id[t], i2 = id[ixj];
                bool before = (v1 > v2) || (v1 == v2 && i1 < i2);
                bool desc = ((t & ksz) == 0);
                if (desc ? !before : before) {
                    v[t] = v2; v[ixj] = v1;
                    id[t] = i2; id[ixj] = i1;
                }
            }
            __syncthreads();
        }
    }

    if (t < LEFT) out_idx[bb * LEFT + t] = (float)id[t];
    // broadcast index [LEFT, CT]
    float* dst = out_index + (size_t)bb * LEFT * CT;
    for (int e = t; e < LEFT * CT; e += 256) {
        dst[e] = (float)id[e / CT];
    }
}

// ---------------------------------------------------------------------------
extern "C" void kernel_launch(void* const* d_in, const int* in_sizes, int n_in,
                              void* d_out, int out_size)
{
    const float* x      = (const float*)d_in[0];
    const float* qkv_w  = (const float*)d_in[1];
    const float* qkv_b  = (const float*)d_in[2];
    const float* proj_w = (const float*)d_in[3];
    const float* proj_b = (const float*)d_in[4];

    float* out_o     = (float*)d_out;                          // [64,197,768]
    float* out_index = out_o     + (size_t)BB * NT * CT;       // [64,137,768]
    float* out_idx   = out_index + (size_t)BB * LEFT * CT;     // [64,137]
    float* out_cls   = out_idx   + (size_t)BB * LEFT;          // [64,196]

    float* ao_ptr = nullptr;
    cudaGetSymbolAddress((void**)&ao_ptr, g_ao);

    const size_t ATTN_SMEM = (size_t)(NT * KPAD * 2 + 8 * 64 + 8 * NT) * sizeof(float);
    cudaFuncSetAttribute(attn_kernel,
                         cudaFuncAttributeMaxDynamicSharedMemorySize,
                         (int)ATTN_SMEM);

    // 1) QKV projection: [12608,768] x [2304,768]^T -> scatter q,k,v
    gemm_nt<<<dim3(3 * CT / 128, MROWS / 64), 256>>>(
        x, qkv_w, qkv_b, MROWS, 3 * CT, CT, 0, nullptr);

    // 2) attention per (b,h)
    attn_kernel<<<BB * HT, 256, ATTN_SMEM>>>();

    // 3) cls attention head-mean
    cls_reduce<<<BB, 256>>>(out_cls);

    // 4) output projection: [12608,768] x [768,768]^T + bias -> out
    gemm_nt<<<dim3(CT / 128, MROWS / 64), 256>>>(
        ao_ptr, proj_w, proj_b, MROWS, CT, CT, 1, out_o);

    // 5) top-k + index broadcast
    topk_kernel<<<BB, 256>>>(out_cls, out_idx, out_index);
}

// round 3
// speedup vs baseline: 2.0054x; 2.0054x over previous
#include <cuda_runtime.h>
#include <cstdint>
#include <float.h>
#include <math.h>

#define BB   64
#define NT   197
#define CT   768
#define HT   12
#define DT   64
#define LEFT 137
#define MROWS (BB*NT)     // 12608

// device scratch
__device__ float g_q[BB*HT*NT*DT];
__device__ float g_k[BB*HT*NT*DT];
__device__ float g_v[BB*HT*NT*DT];
__device__ float g_ao[BB*NT*CT];
__device__ float g_clsh[BB*HT*(NT-1)];
__device__ float g_wt[BB*HT*CT];
__device__ float g_beta[BB*HT];

// ---------------------------------------------------------------------------
// helpers
// ---------------------------------------------------------------------------
__device__ __forceinline__ uint32_t smem_u32(const void* p) {
    uint32_t a;
    asm("{ .reg .u64 t; cvta.to.shared.u64 t, %1; cvt.u32.u64 %0, t; }" : "=r"(a) : "l"(p));
    return a;
}
__device__ __forceinline__ void cp16(uint32_t saddr, const void* g) {
    asm volatile("cp.async.ca.shared.global [%0], [%1], 16;" :: "r"(saddr), "l"(g));
}
__device__ __forceinline__ void cp_commit() {
    asm volatile("cp.async.commit_group;" ::: "memory");
}
__device__ __forceinline__ void cp_wait0() {
    asm volatile("cp.async.wait_group 0;" ::: "memory");
}
__device__ __forceinline__ uint32_t f2tf32(float v) {
    uint32_t r;
    asm("cvt.rna.tf32.f32 %0, %1;" : "=r"(r) : "f"(v));
    return r;
}
__device__ __forceinline__ void mma_tf32(float c[4], uint32_t a0, uint32_t a1,
                                         uint32_t a2, uint32_t a3,
                                         uint32_t b0, uint32_t b1) {
    asm volatile(
        "mma.sync.aligned.m16n8k8.row.col.f32.tf32.tf32.f32 "
        "{%0,%1,%2,%3}, {%4,%5,%6,%7}, {%8,%9}, {%0,%1,%2,%3};"
        : "+f"(c[0]), "+f"(c[1]), "+f"(c[2]), "+f"(c[3])
        : "r"(a0), "r"(a1), "r"(a2), "r"(a3), "r"(b0), "r"(b1));
}

// ---------------------------------------------------------------------------
// tf32 mma.sync GEMM: C[m,n] = sum_k A[m,k]*B[n,k] + bias[n]
// Block 128x128, BK=32, 256 threads (8 warps, warp tile 64x32).
// SMEM rows padded to 36 floats -> conflict-free fragment loads.
// mode 0: scatter into g_q/g_k/g_v per qkv reshape. mode 1: row-major out.
// ---------------------------------------------------------------------------
#define RS   36                       // smem row stride (floats)
#define BUFE (128*RS)                 // floats per buffer
#define GEMM_SMEM (4*BUFE*4)          // bytes: A0,A1,B0,B1

__global__ __launch_bounds__(256) void gemm_mma(
    const float* __restrict__ A, const float* __restrict__ Bw,
    const float* __restrict__ bias, int M, int N, int K, int mode,
    float* __restrict__ Cout)
{
    extern __shared__ float sm[];
    float* Asm[2] = { sm,            sm + BUFE   };
    float* Bsm[2] = { sm + 2*BUFE,   sm + 3*BUFE };

    const int tid = threadIdx.x, lane = tid & 31, wid = tid >> 5;
    const int bm = blockIdx.y * 128, bn = blockIdx.x * 128;
    const int wm = (wid & 1) * 64, wn = (wid >> 1) * 32;
    const int gr = lane >> 2, lc = lane & 3;

    const uint32_t sA[2] = { smem_u32(Asm[0]), smem_u32(Asm[1]) };
    const uint32_t sB[2] = { smem_u32(Bsm[0]), smem_u32(Bsm[1]) };

    float c[4][4][4];
#pragma unroll
    for (int i = 0; i < 4; i++)
#pragma unroll
        for (int j = 0; j < 4; j++)
#pragma unroll
            for (int r = 0; r < 4; r++) c[i][j][r] = 0.f;

    const int row_l = tid >> 3;          // 0..31 base rows (x4 iters -> 128)
    const int c4 = tid & 7;              // 0..7 float4 within 32-float row chunk

    // prologue: stage 0
    {
#pragma unroll
        for (int it = 0; it < 4; it++) {
            int row = row_l + it * 32;
            int ga = bm + row; if (ga > M - 1) ga = M - 1;
            int gb = bn + row; if (gb > N - 1) gb = N - 1;
            cp16(sA[0] + (uint32_t)(row * RS + c4 * 4) * 4, A  + (size_t)ga * K + c4 * 4);
            cp16(sB[0] + (uint32_t)(row * RS + c4 * 4) * 4, Bw + (size_t)gb * K + c4 * 4);
        }
        cp_commit();
    }

    const int S = K / 32;
    for (int s = 0; s < S; s++) {
        cp_wait0();
        __syncthreads();
        if (s + 1 < S) {
            const int nb = (s + 1) & 1;
            const int k0 = (s + 1) * 32;
#pragma unroll
            for (int it = 0; it < 4; it++) {
                int row = row_l + it * 32;
                int ga = bm + row; if (ga > M - 1) ga = M - 1;
                int gb = bn + row; if (gb > N - 1) gb = N - 1;
                cp16(sA[nb] + (uint32_t)(row * RS + c4 * 4) * 4, A  + (size_t)ga * K + k0 + c4 * 4);
                cp16(sB[nb] + (uint32_t)(row * RS + c4 * 4) * 4, Bw + (size_t)gb * K + k0 + c4 * 4);
            }
            cp_commit();
        }
        const float* Ab = Asm[s & 1];
        const float* Bb = Bsm[s & 1];
#pragma unroll
        for (int kk = 0; kk < 4; kk++) {
            const int kbase = kk * 8;
            uint32_t af[4][4];
#pragma unroll
            for (int mt = 0; mt < 4; mt++) {
                const float* p0 = Ab + (wm + mt * 16 + gr) * RS + kbase + lc;
                const float* p1 = p0 + 8 * RS;
                af[mt][0] = f2tf32(p0[0]);
                af[mt][1] = f2tf32(p1[0]);
                af[mt][2] = f2tf32(p0[4]);
                af[mt][3] = f2tf32(p1[4]);
            }
            uint32_t bf[4][2];
#pragma unroll
            for (int nt = 0; nt < 4; nt++) {
                const float* p = Bb + (wn + nt * 8 + gr) * RS + kbase + lc;
                bf[nt][0] = f2tf32(p[0]);
                bf[nt][1] = f2tf32(p[4]);
            }
#pragma unroll
            for (int mt = 0; mt < 4; mt++)
#pragma unroll
                for (int nt = 0; nt < 4; nt++)
                    mma_tf32(c[mt][nt], af[mt][0], af[mt][1], af[mt][2], af[mt][3],
                             bf[nt][0], bf[nt][1]);
        }
        __syncthreads();
    }

    // epilogue
#pragma unroll
    for (int mt = 0; mt < 4; mt++) {
        const int r0 = bm + wm + mt * 16 + gr;
        const int r1 = r0 + 8;
#pragma unroll
        for (int nt = 0; nt < 4; nt++) {
            const int nc = bn + wn + nt * 8 + lc * 2;
            float2 bv = *(const float2*)(bias + nc);
            float2 o0 = { c[mt][nt][0] + bv.x, c[mt][nt][1] + bv.y };
            float2 o1 = { c[mt][nt][2] + bv.x, c[mt][nt][3] + bv.y };
            if (mode == 0) {
                const int which = nc / CT;
                const int rem = nc % CT;
                const int h = rem / DT, d0 = rem % DT;
                float* dst = (which == 0) ? g_q : (which == 1) ? g_k : g_v;
                if (r0 < M) {
                    int b_ = r0 / NT, tok = r0 % NT;
                    *(float2*)(dst + (((size_t)(b_ * HT + h)) * NT + tok) * DT + d0) = o0;
                }
                if (r1 < M) {
                    int b_ = r1 / NT, tok = r1 % NT;
                    *(float2*)(dst + (((size_t)(b_ * HT + h)) * NT + tok) * DT + d0) = o1;
                }
            } else {
                if (r0 < M) *(float2*)(Cout + (size_t)r0 * N + nc) = o0;
                if (r1 < M) *(float2*)(Cout + (size_t)r1 * N + nc) = o1;
            }
        }
    }
}

// ---------------------------------------------------------------------------
// Attention (fp32 on tf32-derived q,k,v) — out path only.
// ---------------------------------------------------------------------------
#define KPAD 68
__global__ __launch_bounds__(256) void attn_kernel()
{
    extern __shared__ float smf[];
    float* Ks = smf;                      // 197*68
    float* Vs = Ks + NT * KPAD;           // 197*68
    float* qs = Vs + NT * KPAD;           // 8*64
    float* ps = qs + 8 * 64;              // 8*197

    const int bh = blockIdx.x;
    const float* Qg = g_q + (size_t)bh * NT * DT;
    const float* Kg = g_k + (size_t)bh * NT * DT;
    const float* Vg = g_v + (size_t)bh * NT * DT;

    const int tid = threadIdx.x, lane = tid & 31, w = tid >> 5;

    for (int i = tid; i < NT * 16; i += 256) {
        int r = i >> 4, c4 = (i & 15) * 4;
        *(float4*)(Ks + r * KPAD + c4) = *(const float4*)(Kg + r * DT + c4);
        *(float4*)(Vs + r * KPAD + c4) = *(const float4*)(Vg + r * DT + c4);
    }
    __syncthreads();

    const float scale = 0.125f;
    const int b = bh / HT, h = bh % HT;

    int jc[7];
#pragma unroll
    for (int t = 0; t < 7; t++) {
        int j = lane + t * 32;
        jc[t] = (j < NT) ? j : 0;
    }

    for (int qr = w; qr < NT; qr += 8) {
        qs[w * 64 + lane]      = Qg[qr * DT + lane];
        qs[w * 64 + lane + 32] = Qg[qr * DT + lane + 32];
        __syncwarp();

        float acc[7] = {0.f,0.f,0.f,0.f,0.f,0.f,0.f};
        const float* qr2 = qs + w * 64;
#pragma unroll
        for (int d4 = 0; d4 < 16; d4++) {
            float4 qv = *(const float4*)(qr2 + d4 * 4);
#pragma unroll
            for (int t = 0; t < 7; t++) {
                float4 kv = *(const float4*)(Ks + jc[t] * KPAD + d4 * 4);
                acc[t] += qv.x * kv.x + qv.y * kv.y + qv.z * kv.z + qv.w * kv.w;
            }
        }
        float sarr[7];
        float mx = -FLT_MAX;
#pragma unroll
        for (int t = 0; t < 7; t++) {
            int j = lane + t * 32;
            sarr[t] = (j < NT) ? acc[t] * scale : -FLT_MAX;
            mx = fmaxf(mx, sarr[t]);
        }
#pragma unroll
        for (int o = 16; o; o >>= 1) mx = fmaxf(mx, __shfl_xor_sync(~0u, mx, o));

        float sum = 0.f;
#pragma unroll
        for (int t = 0; t < 7; t++) {
            int j = lane + t * 32;
            float e = (j < NT) ? __expf(sarr[t] - mx) : 0.f;
            sarr[t] = e;
            sum += e;
        }
#pragma unroll
        for (int o = 16; o; o >>= 1) sum += __shfl_xor_sync(~0u, sum, o);
        float inv = 1.f / sum;

#pragma unroll
        for (int t = 0; t < 7; t++) {
            int j = lane + t * 32;
            if (j < NT) ps[w * NT + j] = sarr[t] * inv;
        }
        __syncwarp();

        float o0 = 0.f, o1 = 0.f;
        const float* pr = ps + w * NT;
        for (int j = 0; j < NT; j++) {
            float p = pr[j];
            o0 += p * Vs[j * KPAD + lane];
            o1 += p * Vs[j * KPAD + lane + 32];
        }
        float* orow = g_ao + ((size_t)(b * NT + qr)) * CT + h * DT;
        orow[lane]      = o0;
        orow[lane + 32] = o1;
        __syncwarp();
    }
}

// ---------------------------------------------------------------------------
// Exact fp32 cls path: w~[b,h,:] = Wk_h^T q_cls ; beta = q_cls . bk_h
// ---------------------------------------------------------------------------
__global__ __launch_bounds__(256) void cls_prep(
    const float* __restrict__ x, const float* __restrict__ qkv_w,
    const float* __restrict__ qkv_b)
{
    __shared__ float xc[CT];
    __shared__ float part[256];
    __shared__ float qc[64];
    const int bh = blockIdx.x;
    const int b = bh / HT, h = bh % HT;
    const int tid = threadIdx.x;

    for (int c = tid; c < CT; c += 256) xc[c] = x[(size_t)b * NT * CT + c];
    __syncthreads();

    const int d = tid & 63, seg = tid >> 6;
    {
        const float* wrow = qkv_w + (size_t)(h * 64 + d) * CT + seg * 192;
        const float* xr = xc + seg * 192;
        float p = 0.f;
        for (int c = 0; c < 192; c++) p += xr[c] * wrow[c];
        part[tid] = p;
    }
    __syncthreads();
    if (tid < 64)
        qc[tid] = part[tid] + part[tid + 64] + part[tid + 128] + part[tid + 192]
                + qkv_b[h * 64 + tid];
    __syncthreads();

    if (tid == 0) {
        float s = 0.f;
        for (int dd = 0; dd < 64; dd++) s += qc[dd] * qkv_b[CT + h * 64 + dd];
        g_beta[bh] = s;
    }
    for (int c = tid; c < CT; c += 256) {
        float s = 0.f;
        const float* wk = qkv_w + (size_t)(CT + h * 64) * CT + c;
#pragma unroll 8
        for (int dd = 0; dd < 64; dd++) s += qc[dd] * wk[(size_t)dd * CT];
        g_wt[(size_t)bh * CT + c] = s;
    }
}

__global__ __launch_bounds__(256) void cls_score(const float* __restrict__ x)
{
    __shared__ float wts[CT];
    __shared__ float sc[NT];
    __shared__ float red[8];
    const int bh = blockIdx.x;
    const int b = bh / HT;
    const int tid = threadIdx.x, lane = tid & 31, w = tid >> 5;

    for (int c = tid; c < CT; c += 256) wts[c] = g_wt[(size_t)bh * CT + c];
    __syncthreads();
    const float beta = g_beta[bh];

    for (int j = w; j < NT; j += 8) {
        const float* xr = x + ((size_t)b * NT + j) * CT;
        float s = 0.f;
        for (int c = lane; c < CT; c += 32) s += wts[c] * xr[c];
#pragma unroll
        for (int o = 16; o; o >>= 1) s += __shfl_xor_sync(~0u, s, o);
        if (lane == 0) sc[j] = (s + beta) * 0.125f;
    }
    __syncthreads();

    float v = (tid < NT) ? sc[tid] : -FLT_MAX;
    float mx = v;
#pragma unroll
    for (int o = 16; o; o >>= 1) mx = fmaxf(mx, __shfl_xor_sync(~0u, mx, o));
    if (lane == 0) red[w] = mx;
    __syncthreads();
    mx = red[0];
#pragma unroll
    for (int i = 1; i < 8; i++) mx = fmaxf(mx, red[i]);

    float e = (tid < NT) ? __expf(v - mx) : 0.f;
    float sum = e;
#pragma unroll
    for (int o = 16; o; o >>= 1) sum += __shfl_xor_sync(~0u, sum, o);
    __syncthreads();
    if (lane == 0) red[w] = sum;
    __syncthreads();
    sum = red[0];
#pragma unroll
    for (int i = 1; i < 8; i++) sum += red[i];

    if (tid >= 1 && tid < NT)
        g_clsh[(size_t)bh * (NT - 1) + (tid - 1)] = e / sum;
}

__global__ void cls_reduce(float* __restrict__ out_cls)
{
    int bb = blockIdx.x;
    int j = threadIdx.x;
    if (j < NT - 1) {
        float s = 0.f;
#pragma unroll
        for (int hh = 0; hh < HT; hh++)
            s += g_clsh[((size_t)(bb * HT + hh)) * (NT - 1) + j];
        out_cls[bb * (NT - 1) + j] = s * (1.f / 12.f);
    }
}

// ---------------------------------------------------------------------------
// Top-k per batch (bitonic 256, val desc / idx asc) + index broadcast
// ---------------------------------------------------------------------------
__global__ __launch_bounds__(256) void topk_kernel(
    const float* __restrict__ cls, float* __restrict__ out_idx,
    float* __restrict__ out_index)
{
    __shared__ float v[256];
    __shared__ int   id[256];
    const int bb = blockIdx.x;
    const int t = threadIdx.x;

    v[t]  = (t < NT - 1) ? cls[bb * (NT - 1) + t] : -FLT_MAX;
    id[t] = t;
    __syncthreads();

    for (int ksz = 2; ksz <= 256; ksz <<= 1) {
        for (int j = ksz >> 1; j > 0; j >>= 1) {
            int ixj = t ^ j;
            if (ixj > t) {
                float v1 = v[t], v2 = v[ixj];
                int i1 = id[t], i2 = id[ixj];
                bool before = (v1 > v2) || (v1 == v2 && i1 < i2);
                bool desc = ((t & ksz) == 0);
                if (desc ? !before : before) {
                    v[t] = v2; v[ixj] = v1;
                    id[t] = i2; id[ixj] = i1;
                }
            }
            __syncthreads();
        }
    }

    if (t < LEFT) out_idx[bb * LEFT + t] = (float)id[t];
    float* dst = out_index + (size_t)bb * LEFT * CT;
    for (int e = t; e < LEFT * CT; e += 256) dst[e] = (float)id[e / CT];
}

// ---------------------------------------------------------------------------
extern "C" void kernel_launch(void* const* d_in, const int* in_sizes, int n_in,
                              void* d_out, int out_size)
{
    const float* x      = (const float*)d_in[0];
    const float* qkv_w  = (const float*)d_in[1];
    const float* qkv_b  = (const float*)d_in[2];
    const float* proj_w = (const float*)d_in[3];
    const float* proj_b = (const float*)d_in[4];

    float* out_o     = (float*)d_out;
    float* out_index = out_o     + (size_t)BB * NT * CT;
    float* out_idx   = out_index + (size_t)BB * LEFT * CT;
    float* out_cls   = out_idx   + (size_t)BB * LEFT;

    float* ao_ptr = nullptr;
    cudaGetSymbolAddress((void**)&ao_ptr, g_ao);

    const size_t ATTN_SMEM = (size_t)(NT * KPAD * 2 + 8 * 64 + 8 * NT) * sizeof(float);
    cudaFuncSetAttribute(attn_kernel, cudaFuncAttributeMaxDynamicSharedMemorySize, (int)ATTN_SMEM);
    cudaFuncSetAttribute(gemm_mma, cudaFuncAttributeMaxDynamicSharedMemorySize, GEMM_SMEM);

    const int mby = (MROWS + 127) / 128;   // 99

    // 1) qkv projection (tf32 mma) -> scatter q,k,v
    gemm_mma<<<dim3(3 * CT / 128, mby), 256, GEMM_SMEM>>>(
        x, qkv_w, qkv_b, MROWS, 3 * CT, CT, 0, nullptr);

    // exact fp32 cls path (independent of gemm results)
    cls_prep<<<BB * HT, 256>>>(x, qkv_w, qkv_b);
    cls_score<<<BB * HT, 256>>>(x);
    cls_reduce<<<BB, 256>>>(out_cls);

    // 2) attention
    attn_kernel<<<BB * HT, 256, ATTN_SMEM>>>();

    // 3) output projection (tf32 mma)
    gemm_mma<<<dim3(CT / 128, mby), 256, GEMM_SMEM>>>(
        ao_ptr, proj_w, proj_b, MROWS, CT, CT, 1, out_o);

    // 4) top-k + index broadcast
    topk_kernel<<<BB, 256>>>(out_cls, out_idx, out_index);
}

// round 4
// speedup vs baseline: 2.1122x; 1.0533x over previous
#include <cuda_runtime.h>
#include <cstdint>
#include <float.h>
#include <math.h>

#define BB   64
#define NT   197
#define CT   768
#define HT   12
#define DT   64
#define LEFT 137
#define MROWS (BB*NT)     // 12608

// device scratch
__device__ float g_q[BB*HT*NT*DT];
__device__ float g_k[BB*HT*NT*DT];
__device__ float g_v[BB*HT*NT*DT];
__device__ float g_ao[BB*NT*CT];
__device__ float g_clsh[BB*HT*(NT-1)];
__device__ float g_wt[BB*HT*CT];
__device__ float g_beta[BB*HT];

// ---------------------------------------------------------------------------
// helpers
// ---------------------------------------------------------------------------
__device__ __forceinline__ uint32_t smem_u32(const void* p) {
    uint32_t a;
    asm("{ .reg .u64 t; cvta.to.shared.u64 t, %1; cvt.u32.u64 %0, t; }" : "=r"(a) : "l"(p));
    return a;
}
__device__ __forceinline__ void cp16(uint32_t saddr, const void* g) {
    asm volatile("cp.async.ca.shared.global [%0], [%1], 16;" :: "r"(saddr), "l"(g));
}
__device__ __forceinline__ void cp_commit() {
    asm volatile("cp.async.commit_group;" ::: "memory");
}
__device__ __forceinline__ void cp_wait1() {
    asm volatile("cp.async.wait_group 1;" ::: "memory");
}
__device__ __forceinline__ uint32_t f2tf32(float v) {
    uint32_t r;
    asm("cvt.rna.tf32.f32 %0, %1;" : "=r"(r) : "f"(v));
    return r;
}
__device__ __forceinline__ void mma_tf32(float c[4], uint32_t a0, uint32_t a1,
                                         uint32_t a2, uint32_t a3,
                                         uint32_t b0, uint32_t b1) {
    asm volatile(
        "mma.sync.aligned.m16n8k8.row.col.f32.tf32.tf32.f32 "
        "{%0,%1,%2,%3}, {%4,%5,%6,%7}, {%8,%9}, {%0,%1,%2,%3};"
        : "+f"(c[0]), "+f"(c[1]), "+f"(c[2]), "+f"(c[3])
        : "r"(a0), "r"(a1), "r"(a2), "r"(a3), "r"(b0), "r"(b1));
}

// ---------------------------------------------------------------------------
// tf32 mma.sync GEMM: C[m,n] = sum_k A[m,k]*B[n,k] + bias[n]
// Block 128x128, BK=32, 256 threads (8 warps, warp tile 64x32).
// 3-buffer cp.async pipeline, wait_group<=1, ONE barrier per stage.
// SMEM rows padded to 36 floats -> conflict-free fragment loads.
// mode 0: scatter into g_q/g_k/g_v per qkv reshape. mode 1: row-major out.
// ---------------------------------------------------------------------------
#define RS   36                       // smem row stride (floats)
#define BUFE (128*RS)                 // floats per buffer
#define GEMM_SMEM (6*BUFE*4)          // bytes: A0..A2, B0..B2 (110.6 KB)

__global__ __launch_bounds__(256) void gemm_mma(
    const float* __restrict__ A, const float* __restrict__ Bw,
    const float* __restrict__ bias, int M, int N, int K, int mode,
    float* __restrict__ Cout)
{
    extern __shared__ float sm[];

    const int tid = threadIdx.x, lane = tid & 31, wid = tid >> 5;
    const int bm = blockIdx.y * 128, bn = blockIdx.x * 128;
    const int wm = (wid & 1) * 64, wn = (wid >> 1) * 32;
    const int gr = lane >> 2, lc = lane & 3;

    uint32_t sA[3], sB[3];
#pragma unroll
    for (int i = 0; i < 3; i++) {
        sA[i] = smem_u32(sm + i * BUFE);
        sB[i] = smem_u32(sm + (3 + i) * BUFE);
    }

    float c[4][4][4];
#pragma unroll
    for (int i = 0; i < 4; i++)
#pragma unroll
        for (int j = 0; j < 4; j++)
#pragma unroll
            for (int r = 0; r < 4; r++) c[i][j][r] = 0.f;

    const int row_l = tid >> 3;          // 0..31 base rows (x4 iters -> 128)
    const int c4 = tid & 7;              // 0..7 float4 within 32-float chunk

    // precompute clamped global row bases (per thread, 4 row groups)
    int gA[4], gB[4];
#pragma unroll
    for (int it = 0; it < 4; it++) {
        int row = row_l + it * 32;
        int ga = bm + row; if (ga > M - 1) ga = M - 1;
        int gb = bn + row; if (gb > N - 1) gb = N - 1;
        gA[it] = ga; gB[it] = gb;
    }
    const uint32_t soff = (uint32_t)(row_l * RS + c4 * 4) * 4;
    const uint32_t sstep = (uint32_t)(32 * RS) * 4;

    const int S = K / 32;

    // prologue: stage 0 and 1
#pragma unroll
    for (int ps = 0; ps < 2; ps++) {
        const int k0 = ps * 32;
#pragma unroll
        for (int it = 0; it < 4; it++) {
            cp16(sA[ps] + soff + it * sstep, A  + (size_t)gA[it] * K + k0 + c4 * 4);
            cp16(sB[ps] + soff + it * sstep, Bw + (size_t)gB[it] * K + k0 + c4 * 4);
        }
        cp_commit();
    }

    int cb = 0;                          // compute buffer index
    int lb = 2;                          // load buffer index
    for (int s = 0; s < S; s++) {
        cp_wait1();                      // stage s resident (s+1 may be in flight)
        __syncthreads();

        const int ls = s + 2;
        if (ls < S) {
            const int k0 = ls * 32;
#pragma unroll
            for (int it = 0; it < 4; it++) {
                cp16(sA[lb] + soff + it * sstep, A  + (size_t)gA[it] * K + k0 + c4 * 4);
                cp16(sB[lb] + soff + it * sstep, Bw + (size_t)gB[it] * K + k0 + c4 * 4);
            }
        }
        cp_commit();

        const float* Ab = sm + cb * BUFE;
        const float* Bb = sm + (3 + cb) * BUFE;
#pragma unroll
        for (int kk = 0; kk < 4; kk++) {
            const int kbase = kk * 8;
            uint32_t af[4][4];
#pragma unroll
            for (int mt = 0; mt < 4; mt++) {
                const float* p0 = Ab + (wm + mt * 16 + gr) * RS + kbase + lc;
                const float* p1 = p0 + 8 * RS;
                af[mt][0] = f2tf32(p0[0]);
                af[mt][1] = f2tf32(p1[0]);
                af[mt][2] = f2tf32(p0[4]);
                af[mt][3] = f2tf32(p1[4]);
            }
            uint32_t bf[4][2];
#pragma unroll
            for (int nt = 0; nt < 4; nt++) {
                const float* p = Bb + (wn + nt * 8 + gr) * RS + kbase + lc;
                bf[nt][0] = f2tf32(p[0]);
                bf[nt][1] = f2tf32(p[4]);
            }
#pragma unroll
            for (int mt = 0; mt < 4; mt++)
#pragma unroll
                for (int nt = 0; nt < 4; nt++)
                    mma_tf32(c[mt][nt], af[mt][0], af[mt][1], af[mt][2], af[mt][3],
                             bf[nt][0], bf[nt][1]);
        }
        cb = (cb + 1) % 3;
        lb = (lb + 1) % 3;
    }

    // epilogue
#pragma unroll
    for (int mt = 0; mt < 4; mt++) {
        const int r0 = bm + wm + mt * 16 + gr;
        const int r1 = r0 + 8;
#pragma unroll
        for (int nt = 0; nt < 4; nt++) {
            const int nc = bn + wn + nt * 8 + lc * 2;
            float2 bv = *(const float2*)(bias + nc);
            float2 o0 = { c[mt][nt][0] + bv.x, c[mt][nt][1] + bv.y };
            float2 o1 = { c[mt][nt][2] + bv.x, c[mt][nt][3] + bv.y };
            if (mode == 0) {
                const int which = nc / CT;
                const int rem = nc % CT;
                const int h = rem / DT, d0 = rem % DT;
                float* dst = (which == 0) ? g_q : (which == 1) ? g_k : g_v;
                if (r0 < M) {
                    int b_ = r0 / NT, tok = r0 % NT;
                    *(float2*)(dst + (((size_t)(b_ * HT + h)) * NT + tok) * DT + d0) = o0;
                }
                if (r1 < M) {
                    int b_ = r1 / NT, tok = r1 % NT;
                    *(float2*)(dst + (((size_t)(b_ * HT + h)) * NT + tok) * DT + d0) = o1;
                }
            } else {
                if (r0 < M) *(float2*)(Cout + (size_t)r0 * N + nc) = o0;
                if (r1 < M) *(float2*)(Cout + (size_t)r1 * N + nc) = o1;
            }
        }
    }
}

// ---------------------------------------------------------------------------
// Attention (fp32 on tf32-derived q,k,v) — out path only.
// ---------------------------------------------------------------------------
#define KPAD 68
__global__ __launch_bounds__(256) void attn_kernel()
{
    extern __shared__ float smf[];
    float* Ks = smf;                      // 197*68
    float* Vs = Ks + NT * KPAD;           // 197*68
    float* qs = Vs + NT * KPAD;           // 8*64
    float* ps = qs + 8 * 64;              // 8*197

    const int bh = blockIdx.x;
    const float* Qg = g_q + (size_t)bh * NT * DT;
    const float* Kg = g_k + (size_t)bh * NT * DT;
    const float* Vg = g_v + (size_t)bh * NT * DT;

    const int tid = threadIdx.x, lane = tid & 31, w = tid >> 5;

    for (int i = tid; i < NT * 16; i += 256) {
        int r = i >> 4, c4 = (i & 15) * 4;
        *(float4*)(Ks + r * KPAD + c4) = *(const float4*)(Kg + r * DT + c4);
        *(float4*)(Vs + r * KPAD + c4) = *(const float4*)(Vg + r * DT + c4);
    }
    __syncthreads();

    const float scale = 0.125f;
    const int b = bh / HT, h = bh % HT;

    int jc[7];
#pragma unroll
    for (int t = 0; t < 7; t++) {
        int j = lane + t * 32;
        jc[t] = (j < NT) ? j : 0;
    }

    for (int qr = w; qr < NT; qr += 8) {
        qs[w * 64 + lane]      = Qg[qr * DT + lane];
        qs[w * 64 + lane + 32] = Qg[qr * DT + lane + 32];
        __syncwarp();

        float acc[7] = {0.f,0.f,0.f,0.f,0.f,0.f,0.f};
        const float* qr2 = qs + w * 64;
#pragma unroll
        for (int d4 = 0; d4 < 16; d4++) {
            float4 qv = *(const float4*)(qr2 + d4 * 4);
#pragma unroll
            for (int t = 0; t < 7; t++) {
                float4 kv = *(const float4*)(Ks + jc[t] * KPAD + d4 * 4);
                acc[t] += qv.x * kv.x + qv.y * kv.y + qv.z * kv.z + qv.w * kv.w;
            }
        }
        float sarr[7];
        float mx = -FLT_MAX;
#pragma unroll
        for (int t = 0; t < 7; t++) {
            int j = lane + t * 32;
            sarr[t] = (j < NT) ? acc[t] * scale : -FLT_MAX;
            mx = fmaxf(mx, sarr[t]);
        }
#pragma unroll
        for (int o = 16; o; o >>= 1) mx = fmaxf(mx, __shfl_xor_sync(~0u, mx, o));

        float sum = 0.f;
#pragma unroll
        for (int t = 0; t < 7; t++) {
            int j = lane + t * 32;
            float e = (j < NT) ? __expf(sarr[t] - mx) : 0.f;
            sarr[t] = e;
            sum += e;
        }
#pragma unroll
        for (int o = 16; o; o >>= 1) sum += __shfl_xor_sync(~0u, sum, o);
        float inv = 1.f / sum;

#pragma unroll
        for (int t = 0; t < 7; t++) {
            int j = lane + t * 32;
            if (j < NT) ps[w * NT + j] = sarr[t] * inv;
        }
        __syncwarp();

        float o0 = 0.f, o1 = 0.f;
        const float* pr = ps + w * NT;
        for (int j = 0; j < NT; j++) {
            float p = pr[j];
            o0 += p * Vs[j * KPAD + lane];
            o1 += p * Vs[j * KPAD + lane + 32];
        }
        float* orow = g_ao + ((size_t)(b * NT + qr)) * CT + h * DT;
        orow[lane]      = o0;
        orow[lane + 32] = o1;
        __syncwarp();
    }
}

// ---------------------------------------------------------------------------
// Exact fp32 cls path: w~[b,h,:] = Wk_h^T q_cls ; beta = q_cls . bk_h
// ---------------------------------------------------------------------------
__global__ __launch_bounds__(256) void cls_prep(
    const float* __restrict__ x, const float* __restrict__ qkv_w,
    const float* __restrict__ qkv_b)
{
    __shared__ float xc[CT];
    __shared__ float part[256];
    __shared__ float qc[64];
    const int bh = blockIdx.x;
    const int b = bh / HT, h = bh % HT;
    const int tid = threadIdx.x;

    for (int c = tid; c < CT; c += 256) xc[c] = x[(size_t)b * NT * CT + c];
    __syncthreads();

    const int d = tid & 63, seg = tid >> 6;
    {
        const float* wrow = qkv_w + (size_t)(h * 64 + d) * CT + seg * 192;
        const float* xr = xc + seg * 192;
        float p = 0.f;
        for (int c = 0; c < 192; c++) p += xr[c] * wrow[c];
        part[tid] = p;
    }
    __syncthreads();
    if (tid < 64)
        qc[tid] = part[tid] + part[tid + 64] + part[tid + 128] + part[tid + 192]
                + qkv_b[h * 64 + tid];
    __syncthreads();

    if (tid == 0) {
        float s = 0.f;
        for (int dd = 0; dd < 64; dd++) s += qc[dd] * qkv_b[CT + h * 64 + dd];
        g_beta[bh] = s;
    }
    for (int c = tid; c < CT; c += 256) {
        float s = 0.f;
        const float* wk = qkv_w + (size_t)(CT + h * 64) * CT + c;
#pragma unroll 8
        for (int dd = 0; dd < 64; dd++) s += qc[dd] * wk[(size_t)dd * CT];
        g_wt[(size_t)bh * CT + c] = s;
    }
}

__global__ __launch_bounds__(256) void cls_score(const float* __restrict__ x)
{
    __shared__ float wts[CT];
    __shared__ float sc[NT];
    __shared__ float red[8];
    const int bh = blockIdx.x;
    const int b = bh / HT;
    const int tid = threadIdx.x, lane = tid & 31, w = tid >> 5;

    for (int c = tid; c < CT; c += 256) wts[c] = g_wt[(size_t)bh * CT + c];
    __syncthreads();
    const float beta = g_beta[bh];

    for (int j = w; j < NT; j += 8) {
        const float* xr = x + ((size_t)b * NT + j) * CT;
        float s = 0.f;
        for (int c = lane; c < CT; c += 32) s += wts[c] * xr[c];
#pragma unroll
        for (int o = 16; o; o >>= 1) s += __shfl_xor_sync(~0u, s, o);
        if (lane == 0) sc[j] = (s + beta) * 0.125f;
    }
    __syncthreads();

    float v = (tid < NT) ? sc[tid] : -FLT_MAX;
    float mx = v;
#pragma unroll
    for (int o = 16; o; o >>= 1) mx = fmaxf(mx, __shfl_xor_sync(~0u, mx, o));
    if (lane == 0) red[w] = mx;
    __syncthreads();
    mx = red[0];
#pragma unroll
    for (int i = 1; i < 8; i++) mx = fmaxf(mx, red[i]);

    float e = (tid < NT) ? __expf(v - mx) : 0.f;
    float sum = e;
#pragma unroll
    for (int o = 16; o; o >>= 1) sum += __shfl_xor_sync(~0u, sum, o);
    __syncthreads();
    if (lane == 0) red[w] = sum;
    __syncthreads();
    sum = red[0];
#pragma unroll
    for (int i = 1; i < 8; i++) sum += red[i];

    if (tid >= 1 && tid < NT)
        g_clsh[(size_t)bh * (NT - 1) + (tid - 1)] = e / sum;
}

__global__ void cls_reduce(float* __restrict__ out_cls)
{
    int bb = blockIdx.x;
    int j = threadIdx.x;
    if (j < NT - 1) {
        float s = 0.f;
#pragma unroll
        for (int hh = 0; hh < HT; hh++)
            s += g_clsh[((size_t)(bb * HT + hh)) * (NT - 1) + j];
        out_cls[bb * (NT - 1) + j] = s * (1.f / 12.f);
    }
}

// ---------------------------------------------------------------------------
// Top-k per batch (bitonic 256, val desc / idx asc) + index broadcast
// ---------------------------------------------------------------------------
__global__ __launch_bounds__(256) void topk_kernel(
    const float* __restrict__ cls, float* __restrict__ out_idx,
    float* __restrict__ out_index)
{
    __shared__ float v[256];
    __shared__ int   id[256];
    const int bb = blockIdx.x;
    const int t = threadIdx.x;

    v[t]  = (t < NT - 1) ? cls[bb * (NT - 1) + t] : -FLT_MAX;
    id[t] = t;
    __syncthreads();

    for (int ksz = 2; ksz <= 256; ksz <<= 1) {
        for (int j = ksz >> 1; j > 0; j >>= 1) {
            int ixj = t ^ j;
            if (ixj > t) {
                float v1 = v[t], v2 = v[ixj];
                int i1 = id[t], i2 = id[ixj];
                bool before = (v1 > v2) || (v1 == v2 && i1 < i2);
                bool desc = ((t & ksz) == 0);
                if (desc ? !before : before) {
                    v[t] = v2; v[ixj] = v1;
                    id[t] = i2; id[ixj] = i1;
                }
            }
            __syncthreads();
        }
    }

    if (t < LEFT) out_idx[bb * LEFT + t] = (float)id[t];
    float* dst = out_index + (size_t)bb * LEFT * CT;
    for (int e = t; e < LEFT * CT; e += 256) dst[e] = (float)id[e / CT];
}

// ---------------------------------------------------------------------------
extern "C" void kernel_launch(void* const* d_in, const int* in_sizes, int n_in,
                              void* d_out, int out_size)
{
    const float* x      = (const float*)d_in[0];
    const float* qkv_w  = (const float*)d_in[1];
    const float* qkv_b  = (const float*)d_in[2];
    const float* proj_w = (const float*)d_in[3];
    const float* proj_b = (const float*)d_in[4];

    float* out_o     = (float*)d_out;
    float* out_index = out_o     + (size_t)BB * NT * CT;
    float* out_idx   = out_index + (size_t)BB * LEFT * CT;
    float* out_cls   = out_idx   + (size_t)BB * LEFT;

    float* ao_ptr = nullptr;
    cudaGetSymbolAddress((void**)&ao_ptr, g_ao);

    const size_t ATTN_SMEM = (size_t)(NT * KPAD * 2 + 8 * 64 + 8 * NT) * sizeof(float);
    cudaFuncSetAttribute(attn_kernel, cudaFuncAttributeMaxDynamicSharedMemorySize, (int)ATTN_SMEM);
    cudaFuncSetAttribute(gemm_mma, cudaFuncAttributeMaxDynamicSharedMemorySize, GEMM_SMEM);

    const int mby = (MROWS + 127) / 128;   // 99

    // 1) qkv projection (tf32 mma) -> scatter q,k,v
    gemm_mma<<<dim3(3 * CT / 128, mby), 256, GEMM_SMEM>>>(
        x, qkv_w, qkv_b, MROWS, 3 * CT, CT, 0, nullptr);

    // exact fp32 cls path (independent of gemm results)
    cls_prep<<<BB * HT, 256>>>(x, qkv_w, qkv_b);
    cls_score<<<BB * HT, 256>>>(x);
    cls_reduce<<<BB, 256>>>(out_cls);

    // 2) attention
    attn_kernel<<<BB * HT, 256, ATTN_SMEM>>>();

    // 3) output projection (tf32 mma)
    gemm_mma<<<dim3(CT / 128, mby), 256, GEMM_SMEM>>>(
        ao_ptr, proj_w, proj_b, MROWS, CT, CT, 1, out_o);

    // 4) top-k + index broadcast
    topk_kernel<<<BB, 256>>>(out_cls, out_idx, out_index);
}

// round 5
// speedup vs baseline: 2.4954x; 1.1814x over previous
#include <cuda_runtime.h>
#include <cstdint>
#include <float.h>
#include <math.h>

#define BB   64
#define NT   197
#define CT   768
#define HT   12
#define DT   64
#define LEFT 137
#define MROWS (BB*NT)     // 12608

// device scratch
__device__ float g_q[BB*HT*NT*DT];
__device__ float g_k[BB*HT*NT*DT];
__device__ float g_v[BB*HT*NT*DT];
__device__ float g_ao[BB*NT*CT];
__device__ float g_clsh[BB*HT*(NT-1)];
__device__ float g_wt[BB*HT*CT];
__device__ float g_beta[BB*HT];

// ---------------------------------------------------------------------------
// helpers
// ---------------------------------------------------------------------------
__device__ __forceinline__ uint32_t smem_u32(const void* p) {
    uint32_t a;
    asm("{ .reg .u64 t; cvta.to.shared.u64 t, %1; cvt.u32.u64 %0, t; }" : "=r"(a) : "l"(p));
    return a;
}
__device__ __forceinline__ void cp16(uint32_t saddr, const void* g) {
    asm volatile("cp.async.ca.shared.global [%0], [%1], 16;" :: "r"(saddr), "l"(g));
}
__device__ __forceinline__ void cp_commit() {
    asm volatile("cp.async.commit_group;" ::: "memory");
}
__device__ __forceinline__ void cp_wait1() {
    asm volatile("cp.async.wait_group 1;" ::: "memory");
}
__device__ __forceinline__ uint32_t f2tf32(float v) {
    uint32_t r;
    asm("cvt.rna.tf32.f32 %0, %1;" : "=r"(r) : "f"(v));
    return r;
}
__device__ __forceinline__ void mma_tf32(float c[4], uint32_t a0, uint32_t a1,
                                         uint32_t a2, uint32_t a3,
                                         uint32_t b0, uint32_t b1) {
    asm volatile(
        "mma.sync.aligned.m16n8k8.row.col.f32.tf32.tf32.f32 "
        "{%0,%1,%2,%3}, {%4,%5,%6,%7}, {%8,%9}, {%0,%1,%2,%3};"
        : "+f"(c[0]), "+f"(c[1]), "+f"(c[2]), "+f"(c[3])
        : "r"(a0), "r"(a1), "r"(a2), "r"(a3), "r"(b0), "r"(b1));
}

// ---------------------------------------------------------------------------
// tf32 mma.sync GEMM: C[m,n] = sum_k A[m,k]*B[n,k] + bias[n]
// Block 128x128, BK=32, 256 threads (8 warps, warp tile 64x32).
// 3-buffer cp.async pipeline, wait_group<=1, ONE barrier per stage.
// ---------------------------------------------------------------------------
#define RS   36                       // smem row stride (floats)
#define BUFE (128*RS)                 // floats per buffer
#define GEMM_SMEM (6*BUFE*4)          // bytes

__global__ __launch_bounds__(256) void gemm_mma(
    const float* __restrict__ A, const float* __restrict__ Bw,
    const float* __restrict__ bias, int M, int N, int K, int mode,
    float* __restrict__ Cout)
{
    extern __shared__ float sm[];

    const int tid = threadIdx.x, lane = tid & 31, wid = tid >> 5;
    const int bm = blockIdx.y * 128, bn = blockIdx.x * 128;
    const int wm = (wid & 1) * 64, wn = (wid >> 1) * 32;
    const int gr = lane >> 2, lc = lane & 3;

    uint32_t sA[3], sB[3];
#pragma unroll
    for (int i = 0; i < 3; i++) {
        sA[i] = smem_u32(sm + i * BUFE);
        sB[i] = smem_u32(sm + (3 + i) * BUFE);
    }

    float c[4][4][4];
#pragma unroll
    for (int i = 0; i < 4; i++)
#pragma unroll
        for (int j = 0; j < 4; j++)
#pragma unroll
            for (int r = 0; r < 4; r++) c[i][j][r] = 0.f;

    const int row_l = tid >> 3;
    const int c4 = tid & 7;

    int gA[4], gB[4];
#pragma unroll
    for (int it = 0; it < 4; it++) {
        int row = row_l + it * 32;
        int ga = bm + row; if (ga > M - 1) ga = M - 1;
        int gb = bn + row; if (gb > N - 1) gb = N - 1;
        gA[it] = ga; gB[it] = gb;
    }
    const uint32_t soff = (uint32_t)(row_l * RS + c4 * 4) * 4;
    const uint32_t sstep = (uint32_t)(32 * RS) * 4;

    const int S = K / 32;

#pragma unroll
    for (int ps = 0; ps < 2; ps++) {
        const int k0 = ps * 32;
#pragma unroll
        for (int it = 0; it < 4; it++) {
            cp16(sA[ps] + soff + it * sstep, A  + (size_t)gA[it] * K + k0 + c4 * 4);
            cp16(sB[ps] + soff + it * sstep, Bw + (size_t)gB[it] * K + k0 + c4 * 4);
        }
        cp_commit();
    }

    int cb = 0, lb = 2;
    for (int s = 0; s < S; s++) {
        cp_wait1();
        __syncthreads();

        const int ls = s + 2;
        if (ls < S) {
            const int k0 = ls * 32;
#pragma unroll
            for (int it = 0; it < 4; it++) {
                cp16(sA[lb] + soff + it * sstep, A  + (size_t)gA[it] * K + k0 + c4 * 4);
                cp16(sB[lb] + soff + it * sstep, Bw + (size_t)gB[it] * K + k0 + c4 * 4);
            }
        }
        cp_commit();

        const float* Ab = sm + cb * BUFE;
        const float* Bb = sm + (3 + cb) * BUFE;
#pragma unroll
        for (int kk = 0; kk < 4; kk++) {
            const int kbase = kk * 8;
            uint32_t af[4][4];
#pragma unroll
            for (int mt = 0; mt < 4; mt++) {
                const float* p0 = Ab + (wm + mt * 16 + gr) * RS + kbase + lc;
                const float* p1 = p0 + 8 * RS;
                af[mt][0] = f2tf32(p0[0]);
                af[mt][1] = f2tf32(p1[0]);
                af[mt][2] = f2tf32(p0[4]);
                af[mt][3] = f2tf32(p1[4]);
            }
            uint32_t bf[4][2];
#pragma unroll
            for (int nt = 0; nt < 4; nt++) {
                const float* p = Bb + (wn + nt * 8 + gr) * RS + kbase + lc;
                bf[nt][0] = f2tf32(p[0]);
                bf[nt][1] = f2tf32(p[4]);
            }
#pragma unroll
            for (int mt = 0; mt < 4; mt++)
#pragma unroll
                for (int nt = 0; nt < 4; nt++)
                    mma_tf32(c[mt][nt], af[mt][0], af[mt][1], af[mt][2], af[mt][3],
                             bf[nt][0], bf[nt][1]);
        }
        cb = (cb + 1) % 3;
        lb = (lb + 1) % 3;
    }

#pragma unroll
    for (int mt = 0; mt < 4; mt++) {
        const int r0 = bm + wm + mt * 16 + gr;
        const int r1 = r0 + 8;
#pragma unroll
        for (int nt = 0; nt < 4; nt++) {
            const int nc = bn + wn + nt * 8 + lc * 2;
            float2 bv = *(const float2*)(bias + nc);
            float2 o0 = { c[mt][nt][0] + bv.x, c[mt][nt][1] + bv.y };
            float2 o1 = { c[mt][nt][2] + bv.x, c[mt][nt][3] + bv.y };
            if (mode == 0) {
                const int which = nc / CT;
                const int rem = nc % CT;
                const int h = rem / DT, d0 = rem % DT;
                float* dst = (which == 0) ? g_q : (which == 1) ? g_k : g_v;
                if (r0 < M) {
                    int b_ = r0 / NT, tok = r0 % NT;
                    *(float2*)(dst + (((size_t)(b_ * HT + h)) * NT + tok) * DT + d0) = o0;
                }
                if (r1 < M) {
                    int b_ = r1 / NT, tok = r1 % NT;
                    *(float2*)(dst + (((size_t)(b_ * HT + h)) * NT + tok) * DT + d0) = o1;
                }
            } else {
                if (r0 < M) *(float2*)(Cout + (size_t)r0 * N + nc) = o0;
                if (r1 < M) *(float2*)(Cout + (size_t)r1 * N + nc) = o1;
            }
        }
    }
}

// ---------------------------------------------------------------------------
// Fused mma attention: one block per (b,h, 64-row q-tile). grid = BB*HT*4.
// S = (Q*scale) K^T via split-tf32 (3 mma, ~fp32 scores); softmax in smem;
// out = P V via tf32 mma. Stride 228 (=4 mod 32) -> conflict-free frag loads.
// ---------------------------------------------------------------------------
#define QSP 68
#define SSP 228
#define AT2_SMEM ((64*QSP + 224*QSP + 64*SSP + 64*SSP) * 4)   // 195072 B

__global__ __launch_bounds__(256) void attn_mma()
{
    extern __shared__ float smf[];
    float* Qs = smf;                         // 64 x QSP
    float* Ks = smf + 64 * QSP;              // 224 x QSP
    float* Vt = smf + 64 * QSP + 224 * QSP;  // 64 x SSP (V transposed)
    float* Ss = Vt + 64 * SSP;               // 64 x SSP

    const int tid = threadIdx.x, lane = tid & 31, wid = tid >> 5;
    const int gr = lane >> 2, lc = lane & 3;
    const int blk = blockIdx.x;
    const int bh = blk >> 2, qt = blk & 3;
    const int qbase = qt * 64;
    const int b = bh / HT, h = bh % HT;
    const int rows_valid = (NT - qbase < 64) ? (NT - qbase) : 64;

    const float* Qg = g_q + (size_t)bh * NT * DT;
    const float* Kg = g_k + (size_t)bh * NT * DT;
    const float* Vg = g_v + (size_t)bh * NT * DT;

    // stage Q (pre-scaled)
    for (int i = tid; i < 64 * 16; i += 256) {
        int r = i >> 4, c = (i & 15) * 4;
        int src = qbase + r; if (src > NT - 1) src = NT - 1;
        float4 v = *(const float4*)(Qg + (size_t)src * DT + c);
        v.x *= 0.125f; v.y *= 0.125f; v.z *= 0.125f; v.w *= 0.125f;
        *(float4*)(Qs + r * QSP + c) = v;
    }
    // stage K rows 0..196, zero rows 197..223
    for (int i = tid; i < 224 * 16; i += 256) {
        int r = i >> 4, c = (i & 15) * 4;
        float4 v = make_float4(0.f, 0.f, 0.f, 0.f);
        if (r < NT) v = *(const float4*)(Kg + (size_t)r * DT + c);
        *(float4*)(Ks + r * QSP + c) = v;
    }
    // stage V transposed: Vt[d][j] = V[j][d]
    for (int i = tid; i < NT * 16; i += 256) {
        int j = i >> 4, d0 = (i & 15) * 4;
        float4 v = *(const float4*)(Vg + (size_t)j * DT + d0);
        Vt[(d0 + 0) * SSP + j] = v.x;
        Vt[(d0 + 1) * SSP + j] = v.y;
        Vt[(d0 + 2) * SSP + j] = v.z;
        Vt[(d0 + 3) * SSP + j] = v.w;
    }
    // zero Vt cols 197..199 (P is zeroed there; avoid NaN garbage anyway)
    for (int i = tid; i < 64 * 3; i += 256) {
        int d = i / 3, c = NT + (i % 3);
        Vt[d * SSP + c] = 0.f;
    }
    __syncthreads();

    // ---- QK^T (split-tf32: 3 mma) ----
    const int wm = (wid & 1) * 32;
    const int wn = (wid >> 1) * 56;
    float cS[2][7][4];
#pragma unroll
    for (int mt = 0; mt < 2; mt++)
#pragma unroll
        for (int nt = 0; nt < 7; nt++)
#pragma unroll
            for (int r = 0; r < 4; r++) cS[mt][nt][r] = 0.f;

#pragma unroll
    for (int kk = 0; kk < 8; kk++) {
        const int kb = kk * 8;
        uint32_t ah[2][4], al[2][4];
#pragma unroll
        for (int mt = 0; mt < 2; mt++) {
            const float* p0 = Qs + (wm + mt * 16 + gr) * QSP + kb + lc;
            const float* p1 = p0 + 8 * QSP;
            float a0 = p0[0], a1 = p1[0], a2 = p0[4], a3 = p1[4];
            ah[mt][0] = f2tf32(a0); al[mt][0] = f2tf32(a0 - __uint_as_float(ah[mt][0]));
            ah[mt][1] = f2tf32(a1); al[mt][1] = f2tf32(a1 - __uint_as_float(ah[mt][1]));
            ah[mt][2] = f2tf32(a2); al[mt][2] = f2tf32(a2 - __uint_as_float(ah[mt][2]));
            ah[mt][3] = f2tf32(a3); al[mt][3] = f2tf32(a3 - __uint_as_float(ah[mt][3]));
        }
        uint32_t bh_[7][2], bl_[7][2];
#pragma unroll
        for (int nt = 0; nt < 7; nt++) {
            const float* p = Ks + (wn + nt * 8 + gr) * QSP + kb + lc;
            float b0 = p[0], b1 = p[4];
            bh_[nt][0] = f2tf32(b0); bl_[nt][0] = f2tf32(b0 - __uint_as_float(bh_[nt][0]));
            bh_[nt][1] = f2tf32(b1); bl_[nt][1] = f2tf32(b1 - __uint_as_float(bh_[nt][1]));
        }
#pragma unroll
        for (int mt = 0; mt < 2; mt++)
#pragma unroll
            for (int nt = 0; nt < 7; nt++) {
                mma_tf32(cS[mt][nt], ah[mt][0], ah[mt][1], ah[mt][2], ah[mt][3],
                         bh_[nt][0], bh_[nt][1]);
                mma_tf32(cS[mt][nt], ah[mt][0], ah[mt][1], ah[mt][2], ah[mt][3],
                         bl_[nt][0], bl_[nt][1]);
                mma_tf32(cS[mt][nt], al[mt][0], al[mt][1], al[mt][2], al[mt][3],
                         bh_[nt][0], bh_[nt][1]);
            }
    }
    // write S frags to smem
#pragma unroll
    for (int mt = 0; mt < 2; mt++) {
        const int row = wm + mt * 16 + gr;
#pragma unroll
        for (int nt = 0; nt < 7; nt++) {
            const int col = wn + nt * 8 + 2 * lc;
            *(float2*)(Ss + row * SSP + col)       = make_float2(cS[mt][nt][0], cS[mt][nt][1]);
            *(float2*)(Ss + (row + 8) * SSP + col) = make_float2(cS[mt][nt][2], cS[mt][nt][3]);
        }
    }
    __syncthreads();

    // ---- softmax (warp w owns rows w*8 .. w*8+7) ----
    for (int r8 = 0; r8 < 8; r8++) {
        const int r = wid * 8 + r8;
        float vx[7];
        float mx = -FLT_MAX;
#pragma unroll
        for (int t = 0; t < 7; t++) {
            int j = lane + 32 * t;
            vx[t] = (j < NT) ? Ss[r * SSP + j] : -FLT_MAX;
            mx = fmaxf(mx, vx[t]);
        }
#pragma unroll
        for (int o = 16; o; o >>= 1) mx = fmaxf(mx, __shfl_xor_sync(~0u, mx, o));
        float sum = 0.f;
#pragma unroll
        for (int t = 0; t < 7; t++) {
            int j = lane + 32 * t;
            float e = (j < NT) ? __expf(vx[t] - mx) : 0.f;
            vx[t] = e;
            sum += e;
        }
#pragma unroll
        for (int o = 16; o; o >>= 1) sum += __shfl_xor_sync(~0u, sum, o);
        float inv = 1.f / sum;
#pragma unroll
        for (int t = 0; t < 7; t++) {
            int j = lane + 32 * t;
            if (j < NT)        Ss[r * SSP + j] = vx[t] * inv;
            else if (j < 200)  Ss[r * SSP + j] = 0.f;
        }
    }
    __syncthreads();

    // ---- PV (tf32 mma): out[i][d] = sum_j P[i][j] V[j][d] ----
    const int wn2 = (wid >> 1) * 16;
    float cO[2][2][4];
#pragma unroll
    for (int mt = 0; mt < 2; mt++)
#pragma unroll
        for (int nt = 0; nt < 2; nt++)
#pragma unroll
            for (int r = 0; r < 4; r++) cO[mt][nt][r] = 0.f;

#pragma unroll
    for (int kk = 0; kk < 25; kk++) {
        const int kb = kk * 8;
        uint32_t af[2][4];
#pragma unroll
        for (int mt = 0; mt < 2; mt++) {
            const float* p0 = Ss + (wm + mt * 16 + gr) * SSP + kb + lc;
            const float* p1 = p0 + 8 * SSP;
            af[mt][0] = f2tf32(p0[0]);
            af[mt][1] = f2tf32(p1[0]);
            af[mt][2] = f2tf32(p0[4]);
            af[mt][3] = f2tf32(p1[4]);
        }
        uint32_t bf[2][2];
#pragma unroll
        for (int nt = 0; nt < 2; nt++) {
            const float* p = Vt + (wn2 + nt * 8 + gr) * SSP + kb + lc;
            bf[nt][0] = f2tf32(p[0]);
            bf[nt][1] = f2tf32(p[4]);
        }
#pragma unroll
        for (int mt = 0; mt < 2; mt++)
#pragma unroll
            for (int nt = 0; nt < 2; nt++)
                mma_tf32(cO[mt][nt], af[mt][0], af[mt][1], af[mt][2], af[mt][3],
                         bf[nt][0], bf[nt][1]);
    }
    // store to g_ao [b, tok, h*64+d]
#pragma unroll
    for (int mt = 0; mt < 2; mt++) {
        const int lr0 = wm + mt * 16 + gr;
        const int lr1 = lr0 + 8;
#pragma unroll
        for (int nt = 0; nt < 2; nt++) {
            const int d = wn2 + nt * 8 + 2 * lc;
            if (lr0 < rows_valid)
                *(float2*)(g_ao + ((size_t)(b * NT + qbase + lr0)) * CT + h * DT + d)
                    = make_float2(cO[mt][nt][0], cO[mt][nt][1]);
            if (lr1 < rows_valid)
                *(float2*)(g_ao + ((size_t)(b * NT + qbase + lr1)) * CT + h * DT + d)
                    = make_float2(cO[mt][nt][2], cO[mt][nt][3]);
        }
    }
}

// ---------------------------------------------------------------------------
// Exact fp32 cls path: w~[b,h,:] = Wk_h^T q_cls ; beta = q_cls . bk_h
// ---------------------------------------------------------------------------
__global__ __launch_bounds__(256) void cls_prep(
    const float* __restrict__ x, const float* __restrict__ qkv_w,
    const float* __restrict__ qkv_b)
{
    __shared__ float xc[CT];
    __shared__ float part[256];
    __shared__ float qc[64];
    const int bh = blockIdx.x;
    const int b = bh / HT, h = bh % HT;
    const int tid = threadIdx.x;

    for (int c = tid; c < CT; c += 256) xc[c] = x[(size_t)b * NT * CT + c];
    __syncthreads();

    const int d = tid & 63, seg = tid >> 6;
    {
        const float* wrow = qkv_w + (size_t)(h * 64 + d) * CT + seg * 192;
        const float* xr = xc + seg * 192;
        float p = 0.f;
        for (int c = 0; c < 192; c++) p += xr[c] * wrow[c];
        part[tid] = p;
    }
    __syncthreads();
    if (tid < 64)
        qc[tid] = part[tid] + part[tid + 64] + part[tid + 128] + part[tid + 192]
                + qkv_b[h * 64 + tid];
    __syncthreads();

    if (tid == 0) {
        float s = 0.f;
        for (int dd = 0; dd < 64; dd++) s += qc[dd] * qkv_b[CT + h * 64 + dd];
        g_beta[bh] = s;
    }
    for (int c = tid; c < CT; c += 256) {
        float s = 0.f;
        const float* wk = qkv_w + (size_t)(CT + h * 64) * CT + c;
#pragma unroll 8
        for (int dd = 0; dd < 64; dd++) s += qc[dd] * wk[(size_t)dd * CT];
        g_wt[(size_t)bh * CT + c] = s;
    }
}

__global__ __launch_bounds__(256) void cls_score(const float* __restrict__ x)
{
    __shared__ float wts[CT];
    __shared__ float sc[NT];
    __shared__ float red[8];
    const int bh = blockIdx.x;
    const int b = bh / HT;
    const int tid = threadIdx.x, lane = tid & 31, w = tid >> 5;

    for (int c = tid; c < CT; c += 256) wts[c] = g_wt[(size_t)bh * CT + c];
    __syncthreads();
    const float beta = g_beta[bh];

    for (int j = w; j < NT; j += 8) {
        const float* xr = x + ((size_t)b * NT + j) * CT;
        float s = 0.f;
        for (int c = lane; c < CT; c += 32) s += wts[c] * xr[c];
#pragma unroll
        for (int o = 16; o; o >>= 1) s += __shfl_xor_sync(~0u, s, o);
        if (lane == 0) sc[j] = (s + beta) * 0.125f;
    }
    __syncthreads();

    float v = (tid < NT) ? sc[tid] : -FLT_MAX;
    float mx = v;
#pragma unroll
    for (int o = 16; o; o >>= 1) mx = fmaxf(mx, __shfl_xor_sync(~0u, mx, o));
    if (lane == 0) red[w] = mx;
    __syncthreads();
    mx = red[0];
#pragma unroll
    for (int i = 1; i < 8; i++) mx = fmaxf(mx, red[i]);

    float e = (tid < NT) ? __expf(v - mx) : 0.f;
    float sum = e;
#pragma unroll
    for (int o = 16; o; o >>= 1) sum += __shfl_xor_sync(~0u, sum, o);
    __syncthreads();
    if (lane == 0) red[w] = sum;
    __syncthreads();
    sum = red[0];
#pragma unroll
    for (int i = 1; i < 8; i++) sum += red[i];

    if (tid >= 1 && tid < NT)
        g_clsh[(size_t)bh * (NT - 1) + (tid - 1)] = e / sum;
}

__global__ void cls_reduce(float* __restrict__ out_cls)
{
    int bb = blockIdx.x;
    int j = threadIdx.x;
    if (j < NT - 1) {
        float s = 0.f;
#pragma unroll
        for (int hh = 0; hh < HT; hh++)
            s += g_clsh[((size_t)(bb * HT + hh)) * (NT - 1) + j];
        out_cls[bb * (NT - 1) + j] = s * (1.f / 12.f);
    }
}

// ---------------------------------------------------------------------------
// Top-k per batch (bitonic 256, val desc / idx asc) + index broadcast
// ---------------------------------------------------------------------------
__global__ __launch_bounds__(256) void topk_kernel(
    const float* __restrict__ cls, float* __restrict__ out_idx,
    float* __restrict__ out_index)
{
    __shared__ float v[256];
    __shared__ int   id[256];
    const int bb = blockIdx.x;
    const int t = threadIdx.x;

    v[t]  = (t < NT - 1) ? cls[bb * (NT - 1) + t] : -FLT_MAX;
    id[t] = t;
    __syncthreads();

    for (int ksz = 2; ksz <= 256; ksz <<= 1) {
        for (int j = ksz >> 1; j > 0; j >>= 1) {
            int ixj = t ^ j;
            if (ixj > t) {
                float v1 = v[t], v2 = v[ixj];
                int i1 = id[t], i2 = id[ixj];
                bool before = (v1 > v2) || (v1 == v2 && i1 < i2);
                bool desc = ((t & ksz) == 0);
                if (desc ? !before : before) {
                    v[t] = v2; v[ixj] = v1;
                    id[t] = i2; id[ixj] = i1;
                }
            }
            __syncthreads();
        }
    }

    if (t < LEFT) out_idx[bb * LEFT + t] = (float)id[t];
    float* dst = out_index + (size_t)bb * LEFT * CT;
    for (int e = t; e < LEFT * CT; e += 256) dst[e] = (float)id[e / CT];
}

// ---------------------------------------------------------------------------
extern "C" void kernel_launch(void* const* d_in, const int* in_sizes, int n_in,
                              void* d_out, int out_size)
{
    const float* x      = (const float*)d_in[0];
    const float* qkv_w  = (const float*)d_in[1];
    const float* qkv_b  = (const float*)d_in[2];
    const float* proj_w = (const float*)d_in[3];
    const float* proj_b = (const float*)d_in[4];

    float* out_o     = (float*)d_out;
    float* out_index = out_o     + (size_t)BB * NT * CT;
    float* out_idx   = out_index + (size_t)BB * LEFT * CT;
    float* out_cls   = out_idx   + (size_t)BB * LEFT;

    float* ao_ptr = nullptr;
    cudaGetSymbolAddress((void**)&ao_ptr, g_ao);

    cudaFuncSetAttribute(gemm_mma, cudaFuncAttributeMaxDynamicSharedMemorySize, GEMM_SMEM);
    cudaFuncSetAttribute(attn_mma, cudaFuncAttributeMaxDynamicSharedMemorySize, AT2_SMEM);

    const int mby = (MROWS + 127) / 128;   // 99

    // 1) qkv projection (tf32 mma) -> scatter q,k,v
    gemm_mma<<<dim3(3 * CT / 128, mby), 256, GEMM_SMEM>>>(
        x, qkv_w, qkv_b, MROWS, 3 * CT, CT, 0, nullptr);

    // exact fp32 cls path (independent of gemm results)
    cls_prep<<<BB * HT, 256>>>(x, qkv_w, qkv_b);
    cls_score<<<BB * HT, 256>>>(x);
    cls_reduce<<<BB, 256>>>(out_cls);

    // 2) fused mma attention
    attn_mma<<<BB * HT * 4, 256, AT2_SMEM>>>();

    // 3) output projection (tf32 mma)
    gemm_mma<<<dim3(CT / 128, mby), 256, GEMM_SMEM>>>(
        ao_ptr, proj_w, proj_b, MROWS, CT, CT, 1, out_o);

    // 4) top-k + index broadcast
    topk_kernel<<<BB, 256>>>(out_cls, out_idx, out_index);
}